// round 11
// baseline (speedup 1.0000x reference)
#include <cuda_runtime.h>
#include <math.h>
#include <stdint.h>

// ---------------------------------------------------------------------------
#define BDIM   2
#define SEQ    1024
#define DMODEL 768
#define NHEADS 12
#define HDIM   64
#define DMLP   3072
#define TTOK   (BDIM * SEQ)
#define QK_SCALE 0.125f

// ---------------------------------------------------------------------------
static __device__ __align__(16) float g_h[TTOK * DMODEL];
static __device__ __align__(16) float g_qkv[TTOK * 3 * DMODEL];
static __device__ __align__(16) float g_qk[(size_t)BDIM * NHEADS * SEQ * SEQ];
static __device__ __align__(16) float g_attnout[TTOK * DMODEL];
static __device__ __align__(16) float g_x1[TTOK * DMODEL];
static __device__ __align__(16) float g_mlp[(size_t)TTOK * DMLP];

// ---------------------------------------------------------------------------
__global__ void ln_kernel(const float* __restrict__ x, const float* __restrict__ g,
                          const float* __restrict__ b, float* __restrict__ out) {
    int row = blockIdx.x;
    const float* xr = x + (size_t)row * DMODEL;
    float* orow = out + (size_t)row * DMODEL;
    __shared__ float red[256];
    int tid = threadIdx.x;

    float s = 0.f;
    for (int i = tid; i < DMODEL; i += 256) s += xr[i];
    red[tid] = s; __syncthreads();
    for (int k = 128; k > 0; k >>= 1) { if (tid < k) red[tid] += red[tid + k]; __syncthreads(); }
    float mu = red[0] * (1.0f / DMODEL);
    __syncthreads();

    float v = 0.f;
    for (int i = tid; i < DMODEL; i += 256) { float d = xr[i] - mu; v += d * d; }
    red[tid] = v; __syncthreads();
    for (int k = 128; k > 0; k >>= 1) { if (tid < k) red[tid] += red[tid + k]; __syncthreads(); }
    float rstd = rsqrtf(red[0] * (1.0f / DMODEL) + 1e-5f);

    for (int i = tid; i < DMODEL; i += 256)
        orow[i] = (xr[i] - mu) * rstd * g[i] + b[i];
}

__device__ __forceinline__ float gelu_tanh(float x) {
    float x3 = x * x * x;
    float t = tanhf(0.7978845608028654f * (x + 0.044715f * x3));
    return 0.5f * x * (1.0f + t);
}

// ---------------------------------------------------------------------------
__device__ __forceinline__ uint32_t f2tf32(float x) {
    uint32_t y;
    asm("cvt.rna.tf32.f32 %0, %1;" : "=r"(y) : "f"(x));
    return y;
}

__device__ __forceinline__ void mma_tf32(float c[4], const uint32_t a[4], const uint32_t b[2]) {
    asm volatile(
        "mma.sync.aligned.m16n8k8.row.col.f32.tf32.tf32.f32 "
        "{%0,%1,%2,%3}, {%4,%5,%6,%7}, {%8,%9}, {%0,%1,%2,%3};\n"
        : "+f"(c[0]), "+f"(c[1]), "+f"(c[2]), "+f"(c[3])
        : "r"(a[0]), "r"(a[1]), "r"(a[2]), "r"(a[3]), "r"(b[0]), "r"(b[1]));
}

// ---------------------------------------------------------------------------
// tf32 tensor-core NT GEMM (proven, synchronous smem).
// ---------------------------------------------------------------------------
template <int ACT, bool RES>
__global__ __launch_bounds__(256)
void gemm_tf32(const float* __restrict__ A, const float* __restrict__ W,
               const float* __restrict__ bias, const float* __restrict__ res,
               float* __restrict__ C, int M, int N, int K) {
    constexpr int BM = 128, BN = 128, BK = 32;
    __shared__ uint32_t As[BK][BM + 4];
    __shared__ uint32_t Ws[BK][BN + 4];

    int tid = threadIdx.x;
    int lane = tid & 31;
    int warp = tid >> 5;
    int warpM = warp >> 2;
    int warpN = warp & 3;
    int qk_ = lane & 3;
    int qr = lane >> 2;

    const float* Ab = A + (size_t)(blockIdx.y * BM) * K;
    const float* Wb = W + (size_t)(blockIdx.x * BN) * K;

    float acc[4][4][4];
#pragma unroll
    for (int i = 0; i < 4; i++)
#pragma unroll
        for (int j = 0; j < 4; j++)
#pragma unroll
            for (int f = 0; f < 4; f++) acc[i][j][f] = 0.f;

    for (int k0 = 0; k0 < K; k0 += BK) {
#pragma unroll
        for (int e = tid; e < 1024; e += 256) {
            int row = e >> 3, c4 = e & 7;
            float4 a = *(const float4*)(Ab + (size_t)row * K + k0 + c4 * 4);
            As[c4 * 4 + 0][row] = f2tf32(a.x); As[c4 * 4 + 1][row] = f2tf32(a.y);
            As[c4 * 4 + 2][row] = f2tf32(a.z); As[c4 * 4 + 3][row] = f2tf32(a.w);
            float4 w = *(const float4*)(Wb + (size_t)row * K + k0 + c4 * 4);
            Ws[c4 * 4 + 0][row] = f2tf32(w.x); Ws[c4 * 4 + 1][row] = f2tf32(w.y);
            Ws[c4 * 4 + 2][row] = f2tf32(w.z); Ws[c4 * 4 + 3][row] = f2tf32(w.w);
        }
        __syncthreads();

#pragma unroll
        for (int kk = 0; kk < 4; kk++) {
            int kb = kk * 8;
            uint32_t afrag[4][4];
            uint32_t bfrag[4][2];
#pragma unroll
            for (int mt = 0; mt < 4; mt++) {
                int rb = warpM * 64 + mt * 16 + qr;
                afrag[mt][0] = As[kb + qk_][rb];
                afrag[mt][1] = As[kb + qk_][rb + 8];
                afrag[mt][2] = As[kb + qk_ + 4][rb];
                afrag[mt][3] = As[kb + qk_ + 4][rb + 8];
            }
#pragma unroll
            for (int nt = 0; nt < 4; nt++) {
                int cb = warpN * 32 + nt * 8 + qr;
                bfrag[nt][0] = Ws[kb + qk_][cb];
                bfrag[nt][1] = Ws[kb + qk_ + 4][cb];
            }
#pragma unroll
            for (int mt = 0; mt < 4; mt++)
#pragma unroll
                for (int nt = 0; nt < 4; nt++)
                    mma_tf32(acc[mt][nt], afrag[mt], bfrag[nt]);
        }
        __syncthreads();
    }

#pragma unroll
    for (int mt = 0; mt < 4; mt++) {
        int r0 = blockIdx.y * BM + warpM * 64 + mt * 16 + qr;
#pragma unroll
        for (int nt = 0; nt < 4; nt++) {
            int col = blockIdx.x * BN + warpN * 32 + nt * 8 + 2 * qk_;
            float b0 = bias[col], b1 = bias[col + 1];
            float v0 = acc[mt][nt][0] + b0;
            float v1 = acc[mt][nt][1] + b1;
            float v2 = acc[mt][nt][2] + b0;
            float v3 = acc[mt][nt][3] + b1;
            if (ACT == 1) { v0 = gelu_tanh(v0); v1 = gelu_tanh(v1); v2 = gelu_tanh(v2); v3 = gelu_tanh(v3); }
            size_t o0 = (size_t)r0 * N + col;
            size_t o1 = (size_t)(r0 + 8) * N + col;
            if (RES) {
                v0 += res[o0]; v1 += res[o0 + 1];
                v2 += res[o1]; v3 += res[o1 + 1];
            }
            *(float2*)(C + o0) = make_float2(v0, v1);
            *(float2*)(C + o1) = make_float2(v2, v3);
        }
    }
}

// ---------------------------------------------------------------------------
// Batched QK^T — exact fp32 FFMA (proven; protects attn_mean/uncertainty).
// ---------------------------------------------------------------------------
__global__ __launch_bounds__(256)
void qk_kernel() {
    constexpr int BM = 128, BN = 128, BK = 16;
    constexpr int LDA = 3 * DMODEL;
    __shared__ float Qs[BK][BM + 4];
    __shared__ float Ks[BK][BN + 4];
    int bh = blockIdx.z;
    int b = bh / NHEADS, h = bh % NHEADS;
    const float* q  = g_qkv + (size_t)b * SEQ * LDA + h * HDIM;
    const float* kx = g_qkv + (size_t)b * SEQ * LDA + DMODEL + h * HDIM;
    float* out = g_qk + (size_t)bh * SEQ * SEQ;

    int tid = threadIdx.x;
    int tx = tid % 16, ty = tid / 16;
    int bm = blockIdx.y * BM, bn = blockIdx.x * BN;

    float acc[8][8];
#pragma unroll
    for (int i = 0; i < 8; i++)
#pragma unroll
        for (int j = 0; j < 8; j++) acc[i][j] = 0.f;

    for (int k0 = 0; k0 < HDIM; k0 += BK) {
#pragma unroll
        for (int e = tid; e < 512; e += 256) {
            int row = e >> 2, c4 = e & 3;
            float4 a = *(const float4*)(q + (size_t)(bm + row) * LDA + k0 + c4 * 4);
            Qs[c4 * 4 + 0][row] = a.x; Qs[c4 * 4 + 1][row] = a.y;
            Qs[c4 * 4 + 2][row] = a.z; Qs[c4 * 4 + 3][row] = a.w;
            float4 w = *(const float4*)(kx + (size_t)(bn + row) * LDA + k0 + c4 * 4);
            Ks[c4 * 4 + 0][row] = w.x; Ks[c4 * 4 + 1][row] = w.y;
            Ks[c4 * 4 + 2][row] = w.z; Ks[c4 * 4 + 3][row] = w.w;
        }
        __syncthreads();
#pragma unroll
        for (int kk = 0; kk < BK; kk++) {
            float a[8], w[8];
#pragma unroll
            for (int i = 0; i < 8; i++) a[i] = Qs[kk][ty * 8 + i];
#pragma unroll
            for (int j = 0; j < 8; j++) w[j] = Ks[kk][tx * 8 + j];
#pragma unroll
            for (int i = 0; i < 8; i++)
#pragma unroll
                for (int j = 0; j < 8; j++) acc[i][j] = fmaf(a[i], w[j], acc[i][j]);
        }
        __syncthreads();
    }

#pragma unroll
    for (int i = 0; i < 8; i++) {
        int n = bm + ty * 8 + i;
#pragma unroll
        for (int j = 0; j < 8; j++)
            out[(size_t)n * SEQ + bn + tx * 8 + j] = acc[i][j];
    }
}

// ---------------------------------------------------------------------------
// Fused softmax + uncertainty + attn-build. One block per (b, n), 384 thr.
// smem: buf[12][FLD] fp32 only (49.4 KB). u goes straight to global in
// phase 2 and is re-read from L2 in phase 3 — no ubuf, no register cap,
// no spills. Natural occupancy: 2 blocks/SM.
// ---------------------------------------------------------------------------
#define FLD (SEQ + 4)
__global__ __launch_bounds__(384)
void fused_su_kernel(const float* __restrict__ r, const float* __restrict__ cw,
                     const float* __restrict__ cb,
                     float* __restrict__ am_out, float* __restrict__ u_out) {
    extern __shared__ float buf[];                     // [NHEADS][FLD]
    __shared__ float wsh[NHEADS * NHEADS];
    __shared__ float bsh[NHEADS];

    int tid = threadIdx.x;
    int lane = tid & 31;
    int warp = tid >> 5;
    int bb = blockIdx.x / SEQ;
    int n  = blockIdx.x % SEQ;

    if (tid < NHEADS * NHEADS) wsh[tid] = cw[tid];
    if (tid < NHEADS) bsh[tid] = cb[tid];

    const size_t hs = (size_t)SEQ * SEQ;
    size_t rowbase = ((size_t)bb * NHEADS * SEQ + n) * SEQ;

    // Phase 1: warp h loads head h's logit row
    {
        const float4* src = (const float4*)(g_qk + rowbase + (size_t)warp * hs);
        float4* dst4 = (float4*)(buf + warp * FLD);
#pragma unroll
        for (int i = 0; i < SEQ / 4 / 32; i++)
            dst4[lane + i * 32] = src[lane + i * 32];
    }
    __syncthreads();

    // Phase 2: uncertainty -> global directly (one live u at a time)
    for (int m = tid; m < SEQ; m += 384) {
        float qv[NHEADS];
#pragma unroll
        for (int h = 0; h < NHEADS; h++) qv[h] = buf[h * FLD + m];
#pragma unroll
        for (int g = 0; g < NHEADS; g++) {
            float s = bsh[g];
#pragma unroll
            for (int h = 0; h < NHEADS; h++) s = fmaf(qv[h], wsh[g * NHEADS + h], s);
            u_out[rowbase + (size_t)g * hs + m] = 1.0f / (1.0f + expf(-s));
        }
    }
    __syncthreads();   // orders phase-2 global u writes before phase-3 reads (block scope)

    // Phase 3: per-head softmax + attn build (warp h owns head h).
    // u re-read from global (L2 hit: written by this block moments ago).
    {
        float* b_ = buf + warp * FLD;
        const float* u_ = u_out + rowbase + (size_t)warp * hs;
        const float* r_ = r + rowbase + (size_t)warp * hs;
        float* am_ = am_out + rowbase + (size_t)warp * hs;
        float* at_ = g_qk + rowbase + (size_t)warp * hs;

        float mx = -1e30f;
#pragma unroll
        for (int i = 0; i < SEQ / 32; i++) mx = fmaxf(mx, b_[lane + i * 32]);
#pragma unroll
        for (int o = 16; o > 0; o >>= 1) mx = fmaxf(mx, __shfl_xor_sync(0xffffffffu, mx, o));

        float s = 0.f;
#pragma unroll
        for (int i = 0; i < SEQ / 32; i++) {
            int m = lane + i * 32;
            float e = expf((b_[m] - mx) * QK_SCALE);
            b_[m] = e;
            s += e;
        }
#pragma unroll
        for (int o = 16; o > 0; o >>= 1) s += __shfl_xor_sync(0xffffffffu, s, o);
        float inv = 1.0f / s;

#pragma unroll
        for (int i = 0; i < SEQ / 32; i++) {
            int m = lane + i * 32;
            float a = b_[m] * inv;
            am_[m] = a;
            at_[m] = fmaf(u_[m], r_[m], a);
        }
    }
}

// ---------------------------------------------------------------------------
// AV (tf32): out[b,h,n,d] = sum_m attn[n,m] * v[m,d]
// ---------------------------------------------------------------------------
__global__ __launch_bounds__(256)
void av_tf32_kernel(float* __restrict__ outp) {
    constexpr int BM = 128, BK = 32;
    constexpr int LDV = 3 * DMODEL;
    __shared__ uint32_t As[BK][BM + 4];
    __shared__ uint32_t Vs[BK][72];

    int bh = blockIdx.z;
    int b = bh / NHEADS, h = bh % NHEADS;
    const float* attn = g_qk + (size_t)bh * SEQ * SEQ + (size_t)(blockIdx.y * BM) * SEQ;
    const float* v = g_qkv + (size_t)b * SEQ * LDV + 2 * DMODEL + h * HDIM;

    int tid = threadIdx.x;
    int lane = tid & 31;
    int warp = tid >> 5;
    int warpM = warp >> 1;
    int warpN = warp & 1;
    int qk_ = lane & 3;
    int qr = lane >> 2;

    float acc[2][4][4];
#pragma unroll
    for (int i = 0; i < 2; i++)
#pragma unroll
        for (int j = 0; j < 4; j++)
#pragma unroll
            for (int f = 0; f < 4; f++) acc[i][j][f] = 0.f;

    for (int k0 = 0; k0 < SEQ; k0 += BK) {
#pragma unroll
        for (int e = tid; e < 1024; e += 256) {
            int row = e >> 3, c4 = e & 7;
            float4 a = *(const float4*)(attn + (size_t)row * SEQ + k0 + c4 * 4);
            As[c4 * 4 + 0][row] = f2tf32(a.x); As[c4 * 4 + 1][row] = f2tf32(a.y);
            As[c4 * 4 + 2][row] = f2tf32(a.z); As[c4 * 4 + 3][row] = f2tf32(a.w);
        }
#pragma unroll
        for (int e = tid; e < 512; e += 256) {
            int row = e >> 4, c4 = e & 15;
            float4 vv = *(const float4*)(v + (size_t)(k0 + row) * LDV + c4 * 4);
            Vs[row][c4 * 4 + 0] = f2tf32(vv.x); Vs[row][c4 * 4 + 1] = f2tf32(vv.y);
            Vs[row][c4 * 4 + 2] = f2tf32(vv.z); Vs[row][c4 * 4 + 3] = f2tf32(vv.w);
        }
        __syncthreads();

#pragma unroll
        for (int kk = 0; kk < 4; kk++) {
            int kb = kk * 8;
            uint32_t afrag[2][4];
            uint32_t bfrag[4][2];
#pragma unroll
            for (int mt = 0; mt < 2; mt++) {
                int rb = warpM * 32 + mt * 16 + qr;
                afrag[mt][0] = As[kb + qk_][rb];
                afrag[mt][1] = As[kb + qk_][rb + 8];
                afrag[mt][2] = As[kb + qk_ + 4][rb];
                afrag[mt][3] = As[kb + qk_ + 4][rb + 8];
            }
#pragma unroll
            for (int nt = 0; nt < 4; nt++) {
                int cb = warpN * 32 + nt * 8 + qr;
                bfrag[nt][0] = Vs[kb + qk_][cb];
                bfrag[nt][1] = Vs[kb + qk_ + 4][cb];
            }
#pragma unroll
            for (int mt = 0; mt < 2; mt++)
#pragma unroll
                for (int nt = 0; nt < 4; nt++)
                    mma_tf32(acc[mt][nt], afrag[mt], bfrag[nt]);
        }
        __syncthreads();
    }

#pragma unroll
    for (int mt = 0; mt < 2; mt++) {
        int n0 = blockIdx.y * BM + warpM * 32 + mt * 16 + qr;
#pragma unroll
        for (int nt = 0; nt < 4; nt++) {
            int col = h * HDIM + warpN * 32 + nt * 8 + 2 * qk_;
            float* o0 = outp + (size_t)(b * SEQ + n0) * DMODEL + col;
            float* o1 = outp + (size_t)(b * SEQ + n0 + 8) * DMODEL + col;
            *(float2*)o0 = make_float2(acc[mt][nt][0], acc[mt][nt][1]);
            *(float2*)o1 = make_float2(acc[mt][nt][2], acc[mt][nt][3]);
        }
    }
}

// ---------------------------------------------------------------------------
extern "C" void kernel_launch(void* const* d_in, const int* in_sizes, int n_in,
                              void* d_out, int out_size) {
    const float* x      = (const float*)d_in[0];
    const float* r      = (const float*)d_in[1];
    const float* ln1_g  = (const float*)d_in[2];
    const float* ln1_b  = (const float*)d_in[3];
    const float* qkv_w  = (const float*)d_in[4];
    const float* qkv_b  = (const float*)d_in[5];
    const float* conv_w = (const float*)d_in[6];
    const float* conv_b = (const float*)d_in[7];
    const float* proj_w = (const float*)d_in[8];
    const float* proj_b = (const float*)d_in[9];
    const float* ln2_g  = (const float*)d_in[10];
    const float* ln2_b  = (const float*)d_in[11];
    const float* fc1_w  = (const float*)d_in[12];
    const float* fc1_b  = (const float*)d_in[13];
    const float* fc2_w  = (const float*)d_in[14];
    const float* fc2_b  = (const float*)d_in[15];

    float* out    = (float*)d_out;
    float* out_x  = out;
    float* out_am = out + (size_t)TTOK * DMODEL;
    float* out_u  = out_am + (size_t)BDIM * NHEADS * SEQ * SEQ;

    static float *p_h = nullptr, *p_qkv = nullptr, *p_qk = nullptr,
                 *p_ao = nullptr, *p_x1 = nullptr, *p_mlp = nullptr;
    static bool attr_done = false;
    const int fused_smem = NHEADS * FLD * 4;   // 49344
    if (!p_h) {
        cudaGetSymbolAddress((void**)&p_h, g_h);
        cudaGetSymbolAddress((void**)&p_qkv, g_qkv);
        cudaGetSymbolAddress((void**)&p_qk, g_qk);
        cudaGetSymbolAddress((void**)&p_ao, g_attnout);
        cudaGetSymbolAddress((void**)&p_x1, g_x1);
        cudaGetSymbolAddress((void**)&p_mlp, g_mlp);
    }
    if (!attr_done) {
        cudaFuncSetAttribute(fused_su_kernel, cudaFuncAttributeMaxDynamicSharedMemorySize, fused_smem);
        attr_done = true;
    }

    // 1. LN1
    ln_kernel<<<TTOK, 256>>>(x, ln1_g, ln1_b, p_h);

    // 2. QKV (tf32)
    gemm_tf32<0, false><<<dim3(3 * DMODEL / 128, TTOK / 128), 256>>>(
        p_h, qkv_w, qkv_b, nullptr, p_qkv, TTOK, 3 * DMODEL, DMODEL);

    // 3. QK^T raw logits (exact fp32)
    qk_kernel<<<dim3(SEQ / 128, SEQ / 128, BDIM * NHEADS), 256>>>();

    // 4. fused softmax + uncertainty + attn build
    fused_su_kernel<<<BDIM * SEQ, 384, fused_smem>>>(r, conv_w, conv_b, out_am, out_u);

    // 5. AV (tf32)
    av_tf32_kernel<<<dim3(1, SEQ / 128, BDIM * NHEADS), 256>>>(p_ao);

    // 6. proj + residual(x)
    gemm_tf32<0, true><<<dim3(DMODEL / 128, TTOK / 128), 256>>>(
        p_ao, proj_w, proj_b, x, p_x1, TTOK, DMODEL, DMODEL);

    // 7. LN2
    ln_kernel<<<TTOK, 256>>>(p_x1, ln2_g, ln2_b, p_h);

    // 8. fc1 + gelu
    gemm_tf32<1, false><<<dim3(DMLP / 128, TTOK / 128), 256>>>(
        p_h, fc1_w, fc1_b, nullptr, p_mlp, TTOK, DMLP, DMODEL);

    // 9. fc2 + residual(x1)
    gemm_tf32<0, true><<<dim3(DMODEL / 128, TTOK / 128), 256>>>(
        p_mlp, fc2_w, fc2_b, p_x1, out_x, TTOK, DMODEL, DMLP);
}

// round 12
// speedup vs baseline: 1.1814x; 1.1814x over previous
#include <cuda_runtime.h>
#include <math.h>
#include <stdint.h>

// ---------------------------------------------------------------------------
#define BDIM   2
#define SEQ    1024
#define DMODEL 768
#define NHEADS 12
#define HDIM   64
#define DMLP   3072
#define TTOK   (BDIM * SEQ)
#define QK_SCALE 0.125f

// ---------------------------------------------------------------------------
static __device__ __align__(16) float g_h[TTOK * DMODEL];
static __device__ __align__(16) float g_qkv[TTOK * 3 * DMODEL];
static __device__ __align__(16) float g_qk[(size_t)BDIM * NHEADS * SEQ * SEQ];
static __device__ __align__(16) float g_attnout[TTOK * DMODEL];
static __device__ __align__(16) float g_x1[TTOK * DMODEL];
static __device__ __align__(16) float g_mlp[(size_t)TTOK * DMLP];

// ---------------------------------------------------------------------------
__global__ void ln_kernel(const float* __restrict__ x, const float* __restrict__ g,
                          const float* __restrict__ b, float* __restrict__ out) {
    int row = blockIdx.x;
    const float* xr = x + (size_t)row * DMODEL;
    float* orow = out + (size_t)row * DMODEL;
    __shared__ float red[256];
    int tid = threadIdx.x;

    float s = 0.f;
    for (int i = tid; i < DMODEL; i += 256) s += xr[i];
    red[tid] = s; __syncthreads();
    for (int k = 128; k > 0; k >>= 1) { if (tid < k) red[tid] += red[tid + k]; __syncthreads(); }
    float mu = red[0] * (1.0f / DMODEL);
    __syncthreads();

    float v = 0.f;
    for (int i = tid; i < DMODEL; i += 256) { float d = xr[i] - mu; v += d * d; }
    red[tid] = v; __syncthreads();
    for (int k = 128; k > 0; k >>= 1) { if (tid < k) red[tid] += red[tid + k]; __syncthreads(); }
    float rstd = rsqrtf(red[0] * (1.0f / DMODEL) + 1e-5f);

    for (int i = tid; i < DMODEL; i += 256)
        orow[i] = (xr[i] - mu) * rstd * g[i] + b[i];
}

__device__ __forceinline__ float gelu_tanh(float x) {
    float x3 = x * x * x;
    float t = tanhf(0.7978845608028654f * (x + 0.044715f * x3));
    return 0.5f * x * (1.0f + t);
}

// ---------------------------------------------------------------------------
__device__ __forceinline__ uint32_t f2tf32(float x) {
    uint32_t y;
    asm("cvt.rna.tf32.f32 %0, %1;" : "=r"(y) : "f"(x));
    return y;
}

__device__ __forceinline__ void mma_tf32(float c[4], const uint32_t a[4], const uint32_t b[2]) {
    asm volatile(
        "mma.sync.aligned.m16n8k8.row.col.f32.tf32.tf32.f32 "
        "{%0,%1,%2,%3}, {%4,%5,%6,%7}, {%8,%9}, {%0,%1,%2,%3};\n"
        : "+f"(c[0]), "+f"(c[1]), "+f"(c[2]), "+f"(c[3])
        : "r"(a[0]), "r"(a[1]), "r"(a[2]), "r"(a[3]), "r"(b[0]), "r"(b[1]));
}

// ---------------------------------------------------------------------------
// tf32 tensor-core NT GEMM (proven, synchronous smem).
// ---------------------------------------------------------------------------
template <int ACT, bool RES>
__global__ __launch_bounds__(256)
void gemm_tf32(const float* __restrict__ A, const float* __restrict__ W,
               const float* __restrict__ bias, const float* __restrict__ res,
               float* __restrict__ C, int M, int N, int K) {
    constexpr int BM = 128, BN = 128, BK = 32;
    __shared__ uint32_t As[BK][BM + 4];
    __shared__ uint32_t Ws[BK][BN + 4];

    int tid = threadIdx.x;
    int lane = tid & 31;
    int warp = tid >> 5;
    int warpM = warp >> 2;
    int warpN = warp & 3;
    int qk_ = lane & 3;
    int qr = lane >> 2;

    const float* Ab = A + (size_t)(blockIdx.y * BM) * K;
    const float* Wb = W + (size_t)(blockIdx.x * BN) * K;

    float acc[4][4][4];
#pragma unroll
    for (int i = 0; i < 4; i++)
#pragma unroll
        for (int j = 0; j < 4; j++)
#pragma unroll
            for (int f = 0; f < 4; f++) acc[i][j][f] = 0.f;

    for (int k0 = 0; k0 < K; k0 += BK) {
#pragma unroll
        for (int e = tid; e < 1024; e += 256) {
            int row = e >> 3, c4 = e & 7;
            float4 a = *(const float4*)(Ab + (size_t)row * K + k0 + c4 * 4);
            As[c4 * 4 + 0][row] = f2tf32(a.x); As[c4 * 4 + 1][row] = f2tf32(a.y);
            As[c4 * 4 + 2][row] = f2tf32(a.z); As[c4 * 4 + 3][row] = f2tf32(a.w);
            float4 w = *(const float4*)(Wb + (size_t)row * K + k0 + c4 * 4);
            Ws[c4 * 4 + 0][row] = f2tf32(w.x); Ws[c4 * 4 + 1][row] = f2tf32(w.y);
            Ws[c4 * 4 + 2][row] = f2tf32(w.z); Ws[c4 * 4 + 3][row] = f2tf32(w.w);
        }
        __syncthreads();

#pragma unroll
        for (int kk = 0; kk < 4; kk++) {
            int kb = kk * 8;
            uint32_t afrag[4][4];
            uint32_t bfrag[4][2];
#pragma unroll
            for (int mt = 0; mt < 4; mt++) {
                int rb = warpM * 64 + mt * 16 + qr;
                afrag[mt][0] = As[kb + qk_][rb];
                afrag[mt][1] = As[kb + qk_][rb + 8];
                afrag[mt][2] = As[kb + qk_ + 4][rb];
                afrag[mt][3] = As[kb + qk_ + 4][rb + 8];
            }
#pragma unroll
            for (int nt = 0; nt < 4; nt++) {
                int cb = warpN * 32 + nt * 8 + qr;
                bfrag[nt][0] = Ws[kb + qk_][cb];
                bfrag[nt][1] = Ws[kb + qk_ + 4][cb];
            }
#pragma unroll
            for (int mt = 0; mt < 4; mt++)
#pragma unroll
                for (int nt = 0; nt < 4; nt++)
                    mma_tf32(acc[mt][nt], afrag[mt], bfrag[nt]);
        }
        __syncthreads();
    }

#pragma unroll
    for (int mt = 0; mt < 4; mt++) {
        int r0 = blockIdx.y * BM + warpM * 64 + mt * 16 + qr;
#pragma unroll
        for (int nt = 0; nt < 4; nt++) {
            int col = blockIdx.x * BN + warpN * 32 + nt * 8 + 2 * qk_;
            float b0 = bias[col], b1 = bias[col + 1];
            float v0 = acc[mt][nt][0] + b0;
            float v1 = acc[mt][nt][1] + b1;
            float v2 = acc[mt][nt][2] + b0;
            float v3 = acc[mt][nt][3] + b1;
            if (ACT == 1) { v0 = gelu_tanh(v0); v1 = gelu_tanh(v1); v2 = gelu_tanh(v2); v3 = gelu_tanh(v3); }
            size_t o0 = (size_t)r0 * N + col;
            size_t o1 = (size_t)(r0 + 8) * N + col;
            if (RES) {
                v0 += res[o0]; v1 += res[o0 + 1];
                v2 += res[o1]; v3 += res[o1 + 1];
            }
            *(float2*)(C + o0) = make_float2(v0, v1);
            *(float2*)(C + o1) = make_float2(v2, v3);
        }
    }
}

// ---------------------------------------------------------------------------
// Batched QK^T — exact fp32 FFMA, BK=64 (whole K resident, one sync pair).
// Dynamic smem: 2 x 64 x 132 floats = 67584 B.
// ---------------------------------------------------------------------------
__global__ __launch_bounds__(256)
void qk_kernel() {
    constexpr int BM = 128, BK = 64, LDQ = BM + 4;
    constexpr int LDA = 3 * DMODEL;
    extern __shared__ float qsm[];
    float* Qs = qsm;                 // [BK][LDQ]
    float* Ks = qsm + BK * LDQ;      // [BK][LDQ]

    int bh = blockIdx.z;
    int b = bh / NHEADS, h = bh % NHEADS;
    const float* q  = g_qkv + (size_t)b * SEQ * LDA + h * HDIM;
    const float* kx = g_qkv + (size_t)b * SEQ * LDA + DMODEL + h * HDIM;
    float* out = g_qk + (size_t)bh * SEQ * SEQ;

    int tid = threadIdx.x;
    int tx = tid % 16, ty = tid / 16;
    int bm = blockIdx.y * BM, bn = blockIdx.x * BM;

    // Load full 128x64 tiles (16 float4 per row), transposed into [k][row].
#pragma unroll
    for (int e = tid; e < 2048; e += 256) {
        int row = e >> 4, c4 = e & 15;
        float4 a = *(const float4*)(q + (size_t)(bm + row) * LDA + c4 * 4);
        Qs[(c4 * 4 + 0) * LDQ + row] = a.x; Qs[(c4 * 4 + 1) * LDQ + row] = a.y;
        Qs[(c4 * 4 + 2) * LDQ + row] = a.z; Qs[(c4 * 4 + 3) * LDQ + row] = a.w;
        float4 w = *(const float4*)(kx + (size_t)(bn + row) * LDA + c4 * 4);
        Ks[(c4 * 4 + 0) * LDQ + row] = w.x; Ks[(c4 * 4 + 1) * LDQ + row] = w.y;
        Ks[(c4 * 4 + 2) * LDQ + row] = w.z; Ks[(c4 * 4 + 3) * LDQ + row] = w.w;
    }
    __syncthreads();

    float acc[8][8];
#pragma unroll
    for (int i = 0; i < 8; i++)
#pragma unroll
        for (int j = 0; j < 8; j++) acc[i][j] = 0.f;

#pragma unroll 8
    for (int kk = 0; kk < BK; kk++) {
        float a[8], w[8];
        *(float4*)(a)     = *(const float4*)(&Qs[kk * LDQ + ty * 8]);
        *(float4*)(a + 4) = *(const float4*)(&Qs[kk * LDQ + ty * 8 + 4]);
        *(float4*)(w)     = *(const float4*)(&Ks[kk * LDQ + tx * 8]);
        *(float4*)(w + 4) = *(const float4*)(&Ks[kk * LDQ + tx * 8 + 4]);
#pragma unroll
        for (int i = 0; i < 8; i++)
#pragma unroll
            for (int j = 0; j < 8; j++) acc[i][j] = fmaf(a[i], w[j], acc[i][j]);
    }

#pragma unroll
    for (int i = 0; i < 8; i++) {
        int n = bm + ty * 8 + i;
#pragma unroll
        for (int j = 0; j < 8; j += 4)
            *(float4*)(out + (size_t)n * SEQ + bn + tx * 8 + j) =
                make_float4(acc[i][j], acc[i][j + 1], acc[i][j + 2], acc[i][j + 3]);
    }
}

// ---------------------------------------------------------------------------
// Fused softmax + uncertainty + attn-build (R4 structure + register taming).
// One block per (b, n), 384 thr. smem: buf + ubuf, both fp32 [12][FLD].
// g-loop NOT unrolled -> one accumulator live -> low regs -> 2 blocks/SM.
// ---------------------------------------------------------------------------
#define FLD (SEQ + 4)
__global__ __launch_bounds__(384)
void fused_su_kernel(const float* __restrict__ r, const float* __restrict__ cw,
                     const float* __restrict__ cb,
                     float* __restrict__ am_out, float* __restrict__ u_out) {
    extern __shared__ float fsm[];
    float* buf  = fsm;                 // [NHEADS][FLD]
    float* ubuf = fsm + NHEADS * FLD;  // [NHEADS][FLD]
    __shared__ float wsh[NHEADS * NHEADS];
    __shared__ float bsh[NHEADS];

    int tid = threadIdx.x;
    int lane = tid & 31;
    int warp = tid >> 5;
    int bb = blockIdx.x / SEQ;
    int n  = blockIdx.x % SEQ;

    if (tid < NHEADS * NHEADS) wsh[tid] = cw[tid];
    if (tid < NHEADS) bsh[tid] = cb[tid];

    const size_t hs = (size_t)SEQ * SEQ;
    size_t rowbase = ((size_t)bb * NHEADS * SEQ + n) * SEQ;

    // Phase 1: warp h loads head h's logit row
    {
        const float4* src = (const float4*)(g_qk + rowbase + (size_t)warp * hs);
        float4* dst4 = (float4*)(buf + warp * FLD);
#pragma unroll
        for (int i = 0; i < SEQ / 4 / 32; i++)
            dst4[lane + i * 32] = src[lane + i * 32];
    }
    __syncthreads();

    // Phase 2: uncertainty. g-loop kept rolled: one accumulator live.
    for (int m = tid; m < SEQ; m += 384) {
        float qv[NHEADS];
#pragma unroll
        for (int h = 0; h < NHEADS; h++) qv[h] = buf[h * FLD + m];
#pragma unroll 1
        for (int g = 0; g < NHEADS; g++) {
            float s = bsh[g];
#pragma unroll
            for (int h = 0; h < NHEADS; h++) s = fmaf(qv[h], wsh[g * NHEADS + h], s);
            float u = 1.0f / (1.0f + expf(-s));
            ubuf[g * FLD + m] = u;
            u_out[rowbase + (size_t)g * hs + m] = u;
        }
    }
    __syncthreads();

    // Phase 3: per-head softmax + attn build (warp h owns head h)
    {
        float* b_ = buf + warp * FLD;
        const float* u_ = ubuf + warp * FLD;
        const float* r_ = r + rowbase + (size_t)warp * hs;
        float* am_ = am_out + rowbase + (size_t)warp * hs;
        float* at_ = g_qk + rowbase + (size_t)warp * hs;

        float mx = -1e30f;
#pragma unroll 4
        for (int i = 0; i < SEQ / 32; i++) mx = fmaxf(mx, b_[lane + i * 32]);
#pragma unroll
        for (int o = 16; o > 0; o >>= 1) mx = fmaxf(mx, __shfl_xor_sync(0xffffffffu, mx, o));

        float s = 0.f;
#pragma unroll 4
        for (int i = 0; i < SEQ / 32; i++) {
            int m = lane + i * 32;
            float e = expf((b_[m] - mx) * QK_SCALE);
            b_[m] = e;
            s += e;
        }
#pragma unroll
        for (int o = 16; o > 0; o >>= 1) s += __shfl_xor_sync(0xffffffffu, s, o);
        float inv = 1.0f / s;

#pragma unroll 4
        for (int i = 0; i < SEQ / 32; i++) {
            int m = lane + i * 32;
            float a = b_[m] * inv;
            am_[m] = a;
            at_[m] = fmaf(u_[m], r_[m], a);
        }
    }
}

// ---------------------------------------------------------------------------
// AV (tf32): out[b,h,n,d] = sum_m attn[n,m] * v[m,d]
// ---------------------------------------------------------------------------
__global__ __launch_bounds__(256)
void av_tf32_kernel(float* __restrict__ outp) {
    constexpr int BM = 128, BK = 32;
    constexpr int LDV = 3 * DMODEL;
    __shared__ uint32_t As[BK][BM + 4];
    __shared__ uint32_t Vs[BK][72];

    int bh = blockIdx.z;
    int b = bh / NHEADS, h = bh % NHEADS;
    const float* attn = g_qk + (size_t)bh * SEQ * SEQ + (size_t)(blockIdx.y * BM) * SEQ;
    const float* v = g_qkv + (size_t)b * SEQ * LDV + 2 * DMODEL + h * HDIM;

    int tid = threadIdx.x;
    int lane = tid & 31;
    int warp = tid >> 5;
    int warpM = warp >> 1;
    int warpN = warp & 1;
    int qk_ = lane & 3;
    int qr = lane >> 2;

    float acc[2][4][4];
#pragma unroll
    for (int i = 0; i < 2; i++)
#pragma unroll
        for (int j = 0; j < 4; j++)
#pragma unroll
            for (int f = 0; f < 4; f++) acc[i][j][f] = 0.f;

    for (int k0 = 0; k0 < SEQ; k0 += BK) {
#pragma unroll
        for (int e = tid; e < 1024; e += 256) {
            int row = e >> 3, c4 = e & 7;
            float4 a = *(const float4*)(attn + (size_t)row * SEQ + k0 + c4 * 4);
            As[c4 * 4 + 0][row] = f2tf32(a.x); As[c4 * 4 + 1][row] = f2tf32(a.y);
            As[c4 * 4 + 2][row] = f2tf32(a.z); As[c4 * 4 + 3][row] = f2tf32(a.w);
        }
#pragma unroll
        for (int e = tid; e < 512; e += 256) {
            int row = e >> 4, c4 = e & 15;
            float4 vv = *(const float4*)(v + (size_t)(k0 + row) * LDV + c4 * 4);
            Vs[row][c4 * 4 + 0] = f2tf32(vv.x); Vs[row][c4 * 4 + 1] = f2tf32(vv.y);
            Vs[row][c4 * 4 + 2] = f2tf32(vv.z); Vs[row][c4 * 4 + 3] = f2tf32(vv.w);
        }
        __syncthreads();

#pragma unroll
        for (int kk = 0; kk < 4; kk++) {
            int kb = kk * 8;
            uint32_t afrag[2][4];
            uint32_t bfrag[4][2];
#pragma unroll
            for (int mt = 0; mt < 2; mt++) {
                int rb = warpM * 32 + mt * 16 + qr;
                afrag[mt][0] = As[kb + qk_][rb];
                afrag[mt][1] = As[kb + qk_][rb + 8];
                afrag[mt][2] = As[kb + qk_ + 4][rb];
                afrag[mt][3] = As[kb + qk_ + 4][rb + 8];
            }
#pragma unroll
            for (int nt = 0; nt < 4; nt++) {
                int cb = warpN * 32 + nt * 8 + qr;
                bfrag[nt][0] = Vs[kb + qk_][cb];
                bfrag[nt][1] = Vs[kb + qk_ + 4][cb];
            }
#pragma unroll
            for (int mt = 0; mt < 2; mt++)
#pragma unroll
                for (int nt = 0; nt < 4; nt++)
                    mma_tf32(acc[mt][nt], afrag[mt], bfrag[nt]);
        }
        __syncthreads();
    }

#pragma unroll
    for (int mt = 0; mt < 2; mt++) {
        int n0 = blockIdx.y * BM + warpM * 32 + mt * 16 + qr;
#pragma unroll
        for (int nt = 0; nt < 4; nt++) {
            int col = h * HDIM + warpN * 32 + nt * 8 + 2 * qk_;
            float* o0 = outp + (size_t)(b * SEQ + n0) * DMODEL + col;
            float* o1 = outp + (size_t)(b * SEQ + n0 + 8) * DMODEL + col;
            *(float2*)o0 = make_float2(acc[mt][nt][0], acc[mt][nt][1]);
            *(float2*)o1 = make_float2(acc[mt][nt][2], acc[mt][nt][3]);
        }
    }
}

// ---------------------------------------------------------------------------
extern "C" void kernel_launch(void* const* d_in, const int* in_sizes, int n_in,
                              void* d_out, int out_size) {
    const float* x      = (const float*)d_in[0];
    const float* r      = (const float*)d_in[1];
    const float* ln1_g  = (const float*)d_in[2];
    const float* ln1_b  = (const float*)d_in[3];
    const float* qkv_w  = (const float*)d_in[4];
    const float* qkv_b  = (const float*)d_in[5];
    const float* conv_w = (const float*)d_in[6];
    const float* conv_b = (const float*)d_in[7];
    const float* proj_w = (const float*)d_in[8];
    const float* proj_b = (const float*)d_in[9];
    const float* ln2_g  = (const float*)d_in[10];
    const float* ln2_b  = (const float*)d_in[11];
    const float* fc1_w  = (const float*)d_in[12];
    const float* fc1_b  = (const float*)d_in[13];
    const float* fc2_w  = (const float*)d_in[14];
    const float* fc2_b  = (const float*)d_in[15];

    float* out    = (float*)d_out;
    float* out_x  = out;
    float* out_am = out + (size_t)TTOK * DMODEL;
    float* out_u  = out_am + (size_t)BDIM * NHEADS * SEQ * SEQ;

    static float *p_h = nullptr, *p_qkv = nullptr, *p_qk = nullptr,
                 *p_ao = nullptr, *p_x1 = nullptr, *p_mlp = nullptr;
    static bool attr_done = false;
    const int fused_smem = 2 * NHEADS * FLD * 4;          // 98688
    const int qk_smem    = 2 * 64 * (128 + 4) * 4;        // 67584
    if (!p_h) {
        cudaGetSymbolAddress((void**)&p_h, g_h);
        cudaGetSymbolAddress((void**)&p_qkv, g_qkv);
        cudaGetSymbolAddress((void**)&p_qk, g_qk);
        cudaGetSymbolAddress((void**)&p_ao, g_attnout);
        cudaGetSymbolAddress((void**)&p_x1, g_x1);
        cudaGetSymbolAddress((void**)&p_mlp, g_mlp);
    }
    if (!attr_done) {
        cudaFuncSetAttribute(fused_su_kernel, cudaFuncAttributeMaxDynamicSharedMemorySize, fused_smem);
        cudaFuncSetAttribute(qk_kernel, cudaFuncAttributeMaxDynamicSharedMemorySize, qk_smem);
        attr_done = true;
    }

    // 1. LN1
    ln_kernel<<<TTOK, 256>>>(x, ln1_g, ln1_b, p_h);

    // 2. QKV (tf32)
    gemm_tf32<0, false><<<dim3(3 * DMODEL / 128, TTOK / 128), 256>>>(
        p_h, qkv_w, qkv_b, nullptr, p_qkv, TTOK, 3 * DMODEL, DMODEL);

    // 3. QK^T raw logits (exact fp32, BK=64 single-stage)
    qk_kernel<<<dim3(SEQ / 128, SEQ / 128, BDIM * NHEADS), 256, qk_smem>>>();

    // 4. fused softmax + uncertainty + attn build
    fused_su_kernel<<<BDIM * SEQ, 384, fused_smem>>>(r, conv_w, conv_b, out_am, out_u);

    // 5. AV (tf32)
    av_tf32_kernel<<<dim3(1, SEQ / 128, BDIM * NHEADS), 256>>>(p_ao);

    // 6. proj + residual(x)
    gemm_tf32<0, true><<<dim3(DMODEL / 128, TTOK / 128), 256>>>(
        p_ao, proj_w, proj_b, x, p_x1, TTOK, DMODEL, DMODEL);

    // 7. LN2
    ln_kernel<<<TTOK, 256>>>(p_x1, ln2_g, ln2_b, p_h);

    // 8. fc1 + gelu
    gemm_tf32<1, false><<<dim3(DMLP / 128, TTOK / 128), 256>>>(
        p_h, fc1_w, fc1_b, nullptr, p_mlp, TTOK, DMLP, DMODEL);

    // 9. fc2 + residual(x1)
    gemm_tf32<0, true><<<dim3(DMODEL / 128, TTOK / 128), 256>>>(
        p_mlp, fc2_w, fc2_b, p_x1, out_x, TTOK, DMODEL, DMLP);
}

// round 15
// speedup vs baseline: 1.2700x; 1.0751x over previous
#include <cuda_runtime.h>
#include <math.h>
#include <stdint.h>

// ---------------------------------------------------------------------------
#define BDIM   2
#define SEQ    1024
#define DMODEL 768
#define NHEADS 12
#define HDIM   64
#define DMLP   3072
#define TTOK   (BDIM * SEQ)
#define QK_SCALE 0.125f

// ---------------------------------------------------------------------------
static __device__ __align__(16) float g_h[TTOK * DMODEL];
static __device__ __align__(16) float g_qkv[TTOK * 3 * DMODEL];
static __device__ __align__(16) float g_qk[(size_t)BDIM * NHEADS * SEQ * SEQ];
static __device__ __align__(16) float g_attnout[TTOK * DMODEL];
static __device__ __align__(16) float g_x1[TTOK * DMODEL];
static __device__ __align__(16) float g_mlp[(size_t)TTOK * DMLP];

// ---------------------------------------------------------------------------
__global__ void ln_kernel(const float* __restrict__ x, const float* __restrict__ g,
                          const float* __restrict__ b, float* __restrict__ out) {
    int row = blockIdx.x;
    const float* xr = x + (size_t)row * DMODEL;
    float* orow = out + (size_t)row * DMODEL;
    __shared__ float red[256];
    int tid = threadIdx.x;

    float s = 0.f;
    for (int i = tid; i < DMODEL; i += 256) s += xr[i];
    red[tid] = s; __syncthreads();
    for (int k = 128; k > 0; k >>= 1) { if (tid < k) red[tid] += red[tid + k]; __syncthreads(); }
    float mu = red[0] * (1.0f / DMODEL);
    __syncthreads();

    float v = 0.f;
    for (int i = tid; i < DMODEL; i += 256) { float d = xr[i] - mu; v += d * d; }
    red[tid] = v; __syncthreads();
    for (int k = 128; k > 0; k >>= 1) { if (tid < k) red[tid] += red[tid + k]; __syncthreads(); }
    float rstd = rsqrtf(red[0] * (1.0f / DMODEL) + 1e-5f);

    for (int i = tid; i < DMODEL; i += 256)
        orow[i] = (xr[i] - mu) * rstd * g[i] + b[i];
}

__device__ __forceinline__ float gelu_tanh(float x) {
    float x3 = x * x * x;
    float t = tanhf(0.7978845608028654f * (x + 0.044715f * x3));
    return 0.5f * x * (1.0f + t);
}

// ---------------------------------------------------------------------------
__device__ __forceinline__ uint32_t f2tf32(float x) {
    uint32_t y;
    asm("cvt.rna.tf32.f32 %0, %1;" : "=r"(y) : "f"(x));
    return y;
}

__device__ __forceinline__ void mma_tf32(float c[4], const uint32_t a[4], const uint32_t b[2]) {
    asm volatile(
        "mma.sync.aligned.m16n8k8.row.col.f32.tf32.tf32.f32 "
        "{%0,%1,%2,%3}, {%4,%5,%6,%7}, {%8,%9}, {%0,%1,%2,%3};\n"
        : "+f"(c[0]), "+f"(c[1]), "+f"(c[2]), "+f"(c[3])
        : "r"(a[0]), "r"(a[1]), "r"(a[2]), "r"(a[3]), "r"(b[0]), "r"(b[1]));
}

// ---------------------------------------------------------------------------
// tf32 tensor-core NT GEMM with REGISTER-prefetch double buffering:
// next tile's LDGs are issued right after the sync, in flight during the
// mma section; stored to smem at the top of the next iteration.
// Block tile 128x128x32, 8 warps (2x4), warp tile 64x32.
// ---------------------------------------------------------------------------
template <int ACT, bool RES>
__global__ __launch_bounds__(256)
void gemm_tf32(const float* __restrict__ A, const float* __restrict__ W,
               const float* __restrict__ bias, const float* __restrict__ res,
               float* __restrict__ C, int M, int N, int K) {
    constexpr int BM = 128, BN = 128, BK = 32;
    __shared__ uint32_t As[BK][BM + 4];
    __shared__ uint32_t Ws[BK][BN + 4];

    int tid = threadIdx.x;
    int lane = tid & 31;
    int warp = tid >> 5;
    int warpM = warp >> 2;
    int warpN = warp & 3;
    int qk_ = lane & 3;
    int qr = lane >> 2;

    const float* Ab = A + (size_t)(blockIdx.y * BM) * K;
    const float* Wb = W + (size_t)(blockIdx.x * BN) * K;

    float acc[4][4][4];
#pragma unroll
    for (int i = 0; i < 4; i++)
#pragma unroll
        for (int j = 0; j < 4; j++)
#pragma unroll
            for (int f = 0; f < 4; f++) acc[i][j][f] = 0.f;

    const int iters = K / BK;

    // prefetch registers: 4 slots x (A,W), each thread owns e = tid + u*256
    float4 pa[4], pw[4];
#pragma unroll
    for (int u = 0; u < 4; u++) {
        int e = tid + u * 256, row = e >> 3, c4 = e & 7;
        pa[u] = *(const float4*)(Ab + (size_t)row * K + c4 * 4);
        pw[u] = *(const float4*)(Wb + (size_t)row * K + c4 * 4);
    }

    for (int it = 0; it < iters; it++) {
        // store prefetched tile (tf32-converted) to smem
#pragma unroll
        for (int u = 0; u < 4; u++) {
            int e = tid + u * 256, row = e >> 3, c4 = e & 7;
            As[c4 * 4 + 0][row] = f2tf32(pa[u].x); As[c4 * 4 + 1][row] = f2tf32(pa[u].y);
            As[c4 * 4 + 2][row] = f2tf32(pa[u].z); As[c4 * 4 + 3][row] = f2tf32(pa[u].w);
            Ws[c4 * 4 + 0][row] = f2tf32(pw[u].x); Ws[c4 * 4 + 1][row] = f2tf32(pw[u].y);
            Ws[c4 * 4 + 2][row] = f2tf32(pw[u].z); Ws[c4 * 4 + 3][row] = f2tf32(pw[u].w);
        }
        __syncthreads();

        // issue next tile's loads now; they complete during the mma section
        if (it + 1 < iters) {
            int k0n = (it + 1) * BK;
#pragma unroll
            for (int u = 0; u < 4; u++) {
                int e = tid + u * 256, row = e >> 3, c4 = e & 7;
                pa[u] = *(const float4*)(Ab + (size_t)row * K + k0n + c4 * 4);
                pw[u] = *(const float4*)(Wb + (size_t)row * K + k0n + c4 * 4);
            }
        }

#pragma unroll
        for (int kk = 0; kk < 4; kk++) {
            int kb = kk * 8;
            uint32_t afrag[4][4];
            uint32_t bfrag[4][2];
#pragma unroll
            for (int mt = 0; mt < 4; mt++) {
                int rb = warpM * 64 + mt * 16 + qr;
                afrag[mt][0] = As[kb + qk_][rb];
                afrag[mt][1] = As[kb + qk_][rb + 8];
                afrag[mt][2] = As[kb + qk_ + 4][rb];
                afrag[mt][3] = As[kb + qk_ + 4][rb + 8];
            }
#pragma unroll
            for (int nt = 0; nt < 4; nt++) {
                int cb = warpN * 32 + nt * 8 + qr;
                bfrag[nt][0] = Ws[kb + qk_][cb];
                bfrag[nt][1] = Ws[kb + qk_ + 4][cb];
            }
#pragma unroll
            for (int mt = 0; mt < 4; mt++)
#pragma unroll
                for (int nt = 0; nt < 4; nt++)
                    mma_tf32(acc[mt][nt], afrag[mt], bfrag[nt]);
        }
        __syncthreads();
    }

#pragma unroll
    for (int mt = 0; mt < 4; mt++) {
        int r0 = blockIdx.y * BM + warpM * 64 + mt * 16 + qr;
#pragma unroll
        for (int nt = 0; nt < 4; nt++) {
            int col = blockIdx.x * BN + warpN * 32 + nt * 8 + 2 * qk_;
            float b0 = bias[col], b1 = bias[col + 1];
            float v0 = acc[mt][nt][0] + b0;
            float v1 = acc[mt][nt][1] + b1;
            float v2 = acc[mt][nt][2] + b0;
            float v3 = acc[mt][nt][3] + b1;
            if (ACT == 1) { v0 = gelu_tanh(v0); v1 = gelu_tanh(v1); v2 = gelu_tanh(v2); v3 = gelu_tanh(v3); }
            size_t o0 = (size_t)r0 * N + col;
            size_t o1 = (size_t)(r0 + 8) * N + col;
            if (RES) {
                v0 += res[o0]; v1 += res[o0 + 1];
                v2 += res[o1]; v3 += res[o1 + 1];
            }
            *(float2*)(C + o0) = make_float2(v0, v1);
            *(float2*)(C + o1) = make_float2(v2, v3);
        }
    }
}

// ---------------------------------------------------------------------------
// Batched QK^T — exact fp32 FFMA, BK=64 (whole K resident, one sync pair).
// Dynamic smem: 2 x 64 x 132 floats = 67584 B.
// ---------------------------------------------------------------------------
__global__ __launch_bounds__(256)
void qk_kernel() {
    constexpr int BM = 128, BK = 64, LDQ = BM + 4;
    constexpr int LDA = 3 * DMODEL;
    extern __shared__ float qsm[];
    float* Qs = qsm;                 // [BK][LDQ]
    float* Ks = qsm + BK * LDQ;      // [BK][LDQ]

    int bh = blockIdx.z;
    int b = bh / NHEADS, h = bh % NHEADS;
    const float* q  = g_qkv + (size_t)b * SEQ * LDA + h * HDIM;
    const float* kx = g_qkv + (size_t)b * SEQ * LDA + DMODEL + h * HDIM;
    float* out = g_qk + (size_t)bh * SEQ * SEQ;

    int tid = threadIdx.x;
    int tx = tid % 16, ty = tid / 16;
    int bm = blockIdx.y * BM, bn = blockIdx.x * BM;

#pragma unroll
    for (int e = tid; e < 2048; e += 256) {
        int row = e >> 4, c4 = e & 15;
        float4 a = *(const float4*)(q + (size_t)(bm + row) * LDA + c4 * 4);
        Qs[(c4 * 4 + 0) * LDQ + row] = a.x; Qs[(c4 * 4 + 1) * LDQ + row] = a.y;
        Qs[(c4 * 4 + 2) * LDQ + row] = a.z; Qs[(c4 * 4 + 3) * LDQ + row] = a.w;
        float4 w = *(const float4*)(kx + (size_t)(bn + row) * LDA + c4 * 4);
        Ks[(c4 * 4 + 0) * LDQ + row] = w.x; Ks[(c4 * 4 + 1) * LDQ + row] = w.y;
        Ks[(c4 * 4 + 2) * LDQ + row] = w.z; Ks[(c4 * 4 + 3) * LDQ + row] = w.w;
    }
    __syncthreads();

    float acc[8][8];
#pragma unroll
    for (int i = 0; i < 8; i++)
#pragma unroll
        for (int j = 0; j < 8; j++) acc[i][j] = 0.f;

#pragma unroll 8
    for (int kk = 0; kk < BK; kk++) {
        float a[8], w[8];
        *(float4*)(a)     = *(const float4*)(&Qs[kk * LDQ + ty * 8]);
        *(float4*)(a + 4) = *(const float4*)(&Qs[kk * LDQ + ty * 8 + 4]);
        *(float4*)(w)     = *(const float4*)(&Ks[kk * LDQ + tx * 8]);
        *(float4*)(w + 4) = *(const float4*)(&Ks[kk * LDQ + tx * 8 + 4]);
#pragma unroll
        for (int i = 0; i < 8; i++)
#pragma unroll
            for (int j = 0; j < 8; j++) acc[i][j] = fmaf(a[i], w[j], acc[i][j]);
    }

#pragma unroll
    for (int i = 0; i < 8; i++) {
        int n = bm + ty * 8 + i;
#pragma unroll
        for (int j = 0; j < 8; j += 4)
            *(float4*)(out + (size_t)n * SEQ + bn + tx * 8 + j) =
                make_float4(acc[i][j], acc[i][j + 1], acc[i][j + 2], acc[i][j + 3]);
    }
}

// ---------------------------------------------------------------------------
// Fused softmax + uncertainty + attn-build (proven R12 version).
// ---------------------------------------------------------------------------
#define FLD (SEQ + 4)
__global__ __launch_bounds__(384)
void fused_su_kernel(const float* __restrict__ r, const float* __restrict__ cw,
                     const float* __restrict__ cb,
                     float* __restrict__ am_out, float* __restrict__ u_out) {
    extern __shared__ float fsm[];
    float* buf  = fsm;                 // [NHEADS][FLD]
    float* ubuf = fsm + NHEADS * FLD;  // [NHEADS][FLD]
    __shared__ float wsh[NHEADS * NHEADS];
    __shared__ float bsh[NHEADS];

    int tid = threadIdx.x;
    int lane = tid & 31;
    int warp = tid >> 5;
    int bb = blockIdx.x / SEQ;
    int n  = blockIdx.x % SEQ;

    if (tid < NHEADS * NHEADS) wsh[tid] = cw[tid];
    if (tid < NHEADS) bsh[tid] = cb[tid];

    const size_t hs = (size_t)SEQ * SEQ;
    size_t rowbase = ((size_t)bb * NHEADS * SEQ + n) * SEQ;

    {
        const float4* src = (const float4*)(g_qk + rowbase + (size_t)warp * hs);
        float4* dst4 = (float4*)(buf + warp * FLD);
#pragma unroll
        for (int i = 0; i < SEQ / 4 / 32; i++)
            dst4[lane + i * 32] = src[lane + i * 32];
    }
    __syncthreads();

    for (int m = tid; m < SEQ; m += 384) {
        float qv[NHEADS];
#pragma unroll
        for (int h = 0; h < NHEADS; h++) qv[h] = buf[h * FLD + m];
#pragma unroll 1
        for (int g = 0; g < NHEADS; g++) {
            float s = bsh[g];
#pragma unroll
            for (int h = 0; h < NHEADS; h++) s = fmaf(qv[h], wsh[g * NHEADS + h], s);
            float u = 1.0f / (1.0f + expf(-s));
            ubuf[g * FLD + m] = u;
            u_out[rowbase + (size_t)g * hs + m] = u;
        }
    }
    __syncthreads();

    {
        float* b_ = buf + warp * FLD;
        const float* u_ = ubuf + warp * FLD;
        const float* r_ = r + rowbase + (size_t)warp * hs;
        float* am_ = am_out + rowbase + (size_t)warp * hs;
        float* at_ = g_qk + rowbase + (size_t)warp * hs;

        float mx = -1e30f;
#pragma unroll 4
        for (int i = 0; i < SEQ / 32; i++) mx = fmaxf(mx, b_[lane + i * 32]);
#pragma unroll
        for (int o = 16; o > 0; o >>= 1) mx = fmaxf(mx, __shfl_xor_sync(0xffffffffu, mx, o));

        float s = 0.f;
#pragma unroll 4
        for (int i = 0; i < SEQ / 32; i++) {
            int m = lane + i * 32;
            float e = expf((b_[m] - mx) * QK_SCALE);
            b_[m] = e;
            s += e;
        }
#pragma unroll
        for (int o = 16; o > 0; o >>= 1) s += __shfl_xor_sync(0xffffffffu, s, o);
        float inv = 1.0f / s;

#pragma unroll 4
        for (int i = 0; i < SEQ / 32; i++) {
            int m = lane + i * 32;
            float a = b_[m] * inv;
            am_[m] = a;
            at_[m] = fmaf(u_[m], r_[m], a);
        }
    }
}

// ---------------------------------------------------------------------------
// AV (tf32): out[b,h,n,d] = sum_m attn[n,m] * v[m,d]
// ---------------------------------------------------------------------------
__global__ __launch_bounds__(256)
void av_tf32_kernel(float* __restrict__ outp) {
    constexpr int BM = 128, BK = 32;
    constexpr int LDV = 3 * DMODEL;
    __shared__ uint32_t As[BK][BM + 4];
    __shared__ uint32_t Vs[BK][72];

    int bh = blockIdx.z;
    int b = bh / NHEADS, h = bh % NHEADS;
    const float* attn = g_qk + (size_t)bh * SEQ * SEQ + (size_t)(blockIdx.y * BM) * SEQ;
    const float* v = g_qkv + (size_t)b * SEQ * LDV + 2 * DMODEL + h * HDIM;

    int tid = threadIdx.x;
    int lane = tid & 31;
    int warp = tid >> 5;
    int warpM = warp >> 1;
    int warpN = warp & 1;
    int qk_ = lane & 3;
    int qr = lane >> 2;

    float acc[2][4][4];
#pragma unroll
    for (int i = 0; i < 2; i++)
#pragma unroll
        for (int j = 0; j < 4; j++)
#pragma unroll
            for (int f = 0; f < 4; f++) acc[i][j][f] = 0.f;

    for (int k0 = 0; k0 < SEQ; k0 += BK) {
#pragma unroll
        for (int e = tid; e < 1024; e += 256) {
            int row = e >> 3, c4 = e & 7;
            float4 a = *(const float4*)(attn + (size_t)row * SEQ + k0 + c4 * 4);
            As[c4 * 4 + 0][row] = f2tf32(a.x); As[c4 * 4 + 1][row] = f2tf32(a.y);
            As[c4 * 4 + 2][row] = f2tf32(a.z); As[c4 * 4 + 3][row] = f2tf32(a.w);
        }
#pragma unroll
        for (int e = tid; e < 512; e += 256) {
            int row = e >> 4, c4 = e & 15;
            float4 vv = *(const float4*)(v + (size_t)(k0 + row) * LDV + c4 * 4);
            Vs[row][c4 * 4 + 0] = f2tf32(vv.x); Vs[row][c4 * 4 + 1] = f2tf32(vv.y);
            Vs[row][c4 * 4 + 2] = f2tf32(vv.z); Vs[row][c4 * 4 + 3] = f2tf32(vv.w);
        }
        __syncthreads();

#pragma unroll
        for (int kk = 0; kk < 4; kk++) {
            int kb = kk * 8;
            uint32_t afrag[2][4];
            uint32_t bfrag[4][2];
#pragma unroll
            for (int mt = 0; mt < 2; mt++) {
                int rb = warpM * 32 + mt * 16 + qr;
                afrag[mt][0] = As[kb + qk_][rb];
                afrag[mt][1] = As[kb + qk_][rb + 8];
                afrag[mt][2] = As[kb + qk_ + 4][rb];
                afrag[mt][3] = As[kb + qk_ + 4][rb + 8];
            }
#pragma unroll
            for (int nt = 0; nt < 4; nt++) {
                int cb = warpN * 32 + nt * 8 + qr;
                bfrag[nt][0] = Vs[kb + qk_][cb];
                bfrag[nt][1] = Vs[kb + qk_ + 4][cb];
            }
#pragma unroll
            for (int mt = 0; mt < 2; mt++)
#pragma unroll
                for (int nt = 0; nt < 4; nt++)
                    mma_tf32(acc[mt][nt], afrag[mt], bfrag[nt]);
        }
        __syncthreads();
    }

#pragma unroll
    for (int mt = 0; mt < 2; mt++) {
        int n0 = blockIdx.y * BM + warpM * 32 + mt * 16 + qr;
#pragma unroll
        for (int nt = 0; nt < 4; nt++) {
            int col = h * HDIM + warpN * 32 + nt * 8 + 2 * qk_;
            float* o0 = outp + (size_t)(b * SEQ + n0) * DMODEL + col;
            float* o1 = outp + (size_t)(b * SEQ + n0 + 8) * DMODEL + col;
            *(float2*)o0 = make_float2(acc[mt][nt][0], acc[mt][nt][1]);
            *(float2*)o1 = make_float2(acc[mt][nt][2], acc[mt][nt][3]);
        }
    }
}

// ---------------------------------------------------------------------------
extern "C" void kernel_launch(void* const* d_in, const int* in_sizes, int n_in,
                              void* d_out, int out_size) {
    const float* x      = (const float*)d_in[0];
    const float* r      = (const float*)d_in[1];
    const float* ln1_g  = (const float*)d_in[2];
    const float* ln1_b  = (const float*)d_in[3];
    const float* qkv_w  = (const float*)d_in[4];
    const float* qkv_b  = (const float*)d_in[5];
    const float* conv_w = (const float*)d_in[6];
    const float* conv_b = (const float*)d_in[7];
    const float* proj_w = (const float*)d_in[8];
    const float* proj_b = (const float*)d_in[9];
    const float* ln2_g  = (const float*)d_in[10];
    const float* ln2_b  = (const float*)d_in[11];
    const float* fc1_w  = (const float*)d_in[12];
    const float* fc1_b  = (const float*)d_in[13];
    const float* fc2_w  = (const float*)d_in[14];
    const float* fc2_b  = (const float*)d_in[15];

    float* out    = (float*)d_out;
    float* out_x  = out;
    float* out_am = out + (size_t)TTOK * DMODEL;
    float* out_u  = out_am + (size_t)BDIM * NHEADS * SEQ * SEQ;

    static float *p_h = nullptr, *p_qkv = nullptr, *p_qk = nullptr,
                 *p_ao = nullptr, *p_x1 = nullptr, *p_mlp = nullptr;
    static bool attr_done = false;
    const int fused_smem = 2 * NHEADS * FLD * 4;          // 98688
    const int qk_smem    = 2 * 64 * (128 + 4) * 4;        // 67584
    if (!p_h) {
        cudaGetSymbolAddress((void**)&p_h, g_h);
        cudaGetSymbolAddress((void**)&p_qkv, g_qkv);
        cudaGetSymbolAddress((void**)&p_qk, g_qk);
        cudaGetSymbolAddress((void**)&p_ao, g_attnout);
        cudaGetSymbolAddress((void**)&p_x1, g_x1);
        cudaGetSymbolAddress((void**)&p_mlp, g_mlp);
    }
    if (!attr_done) {
        cudaFuncSetAttribute(fused_su_kernel, cudaFuncAttributeMaxDynamicSharedMemorySize, fused_smem);
        cudaFuncSetAttribute(qk_kernel, cudaFuncAttributeMaxDynamicSharedMemorySize, qk_smem);
        attr_done = true;
    }

    // 1. LN1
    ln_kernel<<<TTOK, 256>>>(x, ln1_g, ln1_b, p_h);

    // 2. QKV (tf32, register prefetch)
    gemm_tf32<0, false><<<dim3(3 * DMODEL / 128, TTOK / 128), 256>>>(
        p_h, qkv_w, qkv_b, nullptr, p_qkv, TTOK, 3 * DMODEL, DMODEL);

    // 3. QK^T raw logits (exact fp32, BK=64 single-stage)
    qk_kernel<<<dim3(SEQ / 128, SEQ / 128, BDIM * NHEADS), 256, qk_smem>>>();

    // 4. fused softmax + uncertainty + attn build
    fused_su_kernel<<<BDIM * SEQ, 384, fused_smem>>>(r, conv_w, conv_b, out_am, out_u);

    // 5. AV (tf32)
    av_tf32_kernel<<<dim3(1, SEQ / 128, BDIM * NHEADS), 256>>>(p_ao);

    // 6. proj + residual(x)
    gemm_tf32<0, true><<<dim3(DMODEL / 128, TTOK / 128), 256>>>(
        p_ao, proj_w, proj_b, x, p_x1, TTOK, DMODEL, DMODEL);

    // 7. LN2
    ln_kernel<<<TTOK, 256>>>(p_x1, ln2_g, ln2_b, p_h);

    // 8. fc1 + gelu
    gemm_tf32<1, false><<<dim3(DMLP / 128, TTOK / 128), 256>>>(
        p_h, fc1_w, fc1_b, nullptr, p_mlp, TTOK, DMLP, DMODEL);

    // 9. fc2 + residual(x1)
    gemm_tf32<0, true><<<dim3(DMODEL / 128, TTOK / 128), 256>>>(
        p_mlp, fc2_w, fc2_b, p_x1, out_x, TTOK, DMODEL, DMLP);
}